// round 17
// baseline (speedup 1.0000x reference)
#include <cuda_runtime.h>

// Scratch for the extracted diagonal (allocation-free: __device__ global).
__device__ float g_diag[4096];

// Kernel A: pull diag(W) out of the dense [4096,4096] matrix, then signal
// the dependent scale kernel (PDL) so its launch overlaps ours.
__global__ void extract_diag_kernel(const float* __restrict__ W) {
    int j = blockIdx.x * blockDim.x + threadIdx.x;
    if (j < 4096) {
        g_diag[j] = __ldg(&W[(size_t)j * 4097u]);
    }
    __threadfence();
    cudaTriggerProgrammaticLaunchCompletion();
}

// Kernel B: y = x * diag (columnwise), 8 linear streams, ILP=8.
// Total 8,388,608 float4; Q8 = total/8 = 1,048,576 (multiple of 1024, the
// float4 row width, so all eight elements of a thread share one diag value).
#define Q8 1048576u

__global__ void __launch_bounds__(256) diag_scale_kernel(
        const float4* __restrict__ x, float4* __restrict__ y) {
    const unsigned int i = blockIdx.x * blockDim.x + threadIdx.x;  // < Q8

    // All 8 x-loads front-batched BEFORE the PDL sync (independent of
    // g_diag) — max per-thread MLP, overlaps the extract kernel's tail.
    float4 v0 = __ldcs(&x[i]);
    float4 v1 = __ldcs(&x[i + Q8]);
    float4 v2 = __ldcs(&x[i + 2u * Q8]);
    float4 v3 = __ldcs(&x[i + 3u * Q8]);
    float4 v4 = __ldcs(&x[i + 4u * Q8]);
    float4 v5 = __ldcs(&x[i + 5u * Q8]);
    float4 v6 = __ldcs(&x[i + 6u * Q8]);
    float4 v7 = __ldcs(&x[i + 7u * Q8]);

    // Wait for extract's writes, then one diag load serves all 8 streams.
    cudaGridDependencySynchronize();
    const float4* d4 = reinterpret_cast<const float4*>(g_diag);
    const float4 d = __ldg(&d4[i & 1023u]);

    v0.x *= d.x; v0.y *= d.y; v0.z *= d.z; v0.w *= d.w;
    v1.x *= d.x; v1.y *= d.y; v1.z *= d.z; v1.w *= d.w;
    v2.x *= d.x; v2.y *= d.y; v2.z *= d.z; v2.w *= d.w;
    v3.x *= d.x; v3.y *= d.y; v3.z *= d.z; v3.w *= d.w;
    v4.x *= d.x; v4.y *= d.y; v4.z *= d.z; v4.w *= d.w;
    v5.x *= d.x; v5.y *= d.y; v5.z *= d.z; v5.w *= d.w;
    v6.x *= d.x; v6.y *= d.y; v6.z *= d.z; v6.w *= d.w;
    v7.x *= d.x; v7.y *= d.y; v7.z *= d.z; v7.w *= d.w;

    __stcs(&y[i], v0);
    __stcs(&y[i + Q8], v1);
    __stcs(&y[i + 2u * Q8], v2);
    __stcs(&y[i + 3u * Q8], v3);
    __stcs(&y[i + 4u * Q8], v4);
    __stcs(&y[i + 5u * Q8], v5);
    __stcs(&y[i + 6u * Q8], v6);
    __stcs(&y[i + 7u * Q8], v7);
}

extern "C" void kernel_launch(void* const* d_in, const int* in_sizes, int n_in,
                              void* d_out, int out_size) {
    const float* x = (const float*)d_in[0];
    const float* W = (const float*)d_in[1];
    float* y = (float*)d_out;

    extract_diag_kernel<<<16, 256>>>(W);

    // Scale kernel with programmatic stream serialization: its launch and
    // pre-sync prologue overlap the extract kernel.
    cudaLaunchConfig_t cfg = {};
    cfg.gridDim = dim3(4096);   // Q8 / 256
    cfg.blockDim = dim3(256);
    cfg.dynamicSmemBytes = 0;
    cfg.stream = 0;
    cudaLaunchAttribute attrs[1];
    attrs[0].id = cudaLaunchAttributeProgrammaticStreamSerialization;
    attrs[0].val.programmaticStreamSerializationAllowed = 1;
    cfg.attrs = attrs;
    cfg.numAttrs = 1;
    cudaLaunchKernelEx(&cfg, diag_scale_kernel, (const float4*)x, (float4*)y);
}